// round 9
// baseline (speedup 1.0000x reference)
#include <cuda_runtime.h>
#include <cuda_bf16.h>

// Problem dims (fixed by the dataset)
#define BB 32
#define SS 2048
#define II 256
#define HH 512

// ---------------- scratch (no cudaMalloc allowed) ----------------
__device__ float    g_a[2][BB * HH];   // double-buffered tanh(h) exchange
__device__ unsigned g_bars[4 * 256];   // one counter per batch-group, 1KB apart

__global__ void init_kernel() {
    int idx = blockIdx.x * blockDim.x + threadIdx.x;
    int n = 2 * BB * HH;
    for (int i = idx; i < n; i += gridDim.x * blockDim.x)
        ((float*)g_a)[i] = 0.0f;
    if (blockIdx.x == 0)
        for (int i = threadIdx.x; i < 4 * 256; i += blockDim.x)
            g_bars[i] = 0u;
}

// Packed fp32x2 FMA (Blackwell sm_103a; PTX-only — ptxas never auto-fuses)
#define FMA_F32X2(d, a, b, c) \
    asm("fma.rn.f32x2 %0, %1, %2, %3;" : "=l"(d) : "l"(a), "l"(b), "l"(c))
// Duplicate one fp32 into both lanes of a packed f32x2
#define PACK2_DUP(d, s) \
    asm("mov.b64 %0, {%1, %1};" : "=l"(d) : "r"(s))

// ---------------- Kernel A: xproj = x @ Wx^T + bias  (in-place into d_out) ----
#define BM 64
#define BN 64
#define BK 16

__global__ __launch_bounds__(256) void xproj_kernel(
    const float* __restrict__ x,     // [BB*SS, II]
    const float* __restrict__ Wx,    // [HH, II]
    const float* __restrict__ bias,  // [HH]
    float* __restrict__ out)         // [BB*SS, HH]
{
    __shared__ float As[BK][BM + 4];
    __shared__ float Bs[BK][BN + 4];

    const int tid  = threadIdx.x;
    const int m0   = blockIdx.x * BM;
    const int n0   = blockIdx.y * BN;
    const int lrow = tid >> 2;
    const int lk   = (tid & 3) << 2;
    const int ty   = tid >> 4;
    const int tx   = tid & 15;

    const float* xptr = x  + (size_t)(m0 + lrow) * II;
    const float* wptr = Wx + (size_t)(n0 + lrow) * II;

    long long acc2[4][2];
#pragma unroll
    for (int i = 0; i < 4; i++) { acc2[i][0] = 0; acc2[i][1] = 0; }

    for (int k0 = 0; k0 < II; k0 += BK) {
        float4 xv = *reinterpret_cast<const float4*>(xptr + k0 + lk);
        float4 wv = *reinterpret_cast<const float4*>(wptr + k0 + lk);
        As[lk + 0][lrow] = xv.x; As[lk + 1][lrow] = xv.y;
        As[lk + 2][lrow] = xv.z; As[lk + 3][lrow] = xv.w;
        Bs[lk + 0][lrow] = wv.x; Bs[lk + 1][lrow] = wv.y;
        Bs[lk + 2][lrow] = wv.z; Bs[lk + 3][lrow] = wv.w;
        __syncthreads();

#pragma unroll
        for (int kk = 0; kk < BK; kk++) {
            long long b01 = *reinterpret_cast<const long long*>(&Bs[kk][tx * 4]);
            long long b23 = *reinterpret_cast<const long long*>(&Bs[kk][tx * 4 + 2]);
            long long ap[4];
#pragma unroll
            for (int i = 0; i < 4; i++) {
                float av = As[kk][ty * 4 + i];
                PACK2_DUP(ap[i], __float_as_uint(av));
            }
#pragma unroll
            for (int i = 0; i < 4; i++) {
                FMA_F32X2(acc2[i][0], ap[i], b01, acc2[i][0]);
                FMA_F32X2(acc2[i][1], ap[i], b23, acc2[i][1]);
            }
        }
        __syncthreads();
    }

    float bb[4];
#pragma unroll
    for (int j = 0; j < 4; j++) bb[j] = bias[n0 + tx * 4 + j];

#pragma unroll
    for (int i = 0; i < 4; i++) {
        size_t row = (size_t)(m0 + ty * 4 + i);
        float2 f01 = *reinterpret_cast<float2*>(&acc2[i][0]);
        float2 f23 = *reinterpret_cast<float2*>(&acc2[i][1]);
        float4 v;
        v.x = f01.x + bb[0];
        v.y = f01.y + bb[1];
        v.z = f23.x + bb[2];
        v.w = f23.y + bb[3];
        *reinterpret_cast<float4*>(out + row * HH + n0 + tx * 4) = v;
    }
}

// ---------------- Kernel B: persistent recurrence --------------------------
// 128 CTAs = 32 row-groups x 4 batch-groups, 256 threads each.
// CTA tile: 16 rows x 8 batches. Warp w owns k-segment [64w, 64w+64).
// Lane l: rowg = l&7, batchg = l>>3. Thread computes a 2x2 register block:
//   rows {rowg, rowg+8} x batches {batchg, batchg+4}.
// Per 16B k-chunk: 2 Wh LDS.128 (8 distinct rows on disjoint bank quads,
// 4-way lane bcast, 1 wavefront each) + 2 a LDS.128 (4 distinct batches,
// 8-way bcast, 1 wavefront each) + 8 FFMA2. Stride 516 floats (%32==4,
// 16B-aligned) gives conflict-free bank-quad placement for both arrays.
// Cross-warp k-reduction via psum[8][128]; 128 owner threads (tid =
// batch*16+row) finish the Euler step, publish tanh, store out.
// Sync is per batch-group: 32 CTAs per release/acquire barrier.
#define NCTA 128
#define RPC 16          // rows per CTA
#define BPC 8           // batches per CTA
#define RTHREADS 256
#define GRPCTAS 32      // CTAs per barrier group
#define WST 516         // Wh smem row stride (floats)
#define AST 516         // a  smem row stride (floats)
#define PP  128         // psum slots per warp

#define WH_F (RPC * WST)            // 8256
#define A_F  (BPC * AST)            // 4128
#define PS_F (8 * PP)               // 1024
#define RSMEM_BYTES ((WH_F + A_F + PS_F) * 4)   // 53632

__global__ __launch_bounds__(RTHREADS, 1) void ltc_recur_kernel(
    const float* __restrict__ Wh,    // [HH, HH]
    const float* __restrict__ tau,   // [HH]
    float* __restrict__ out)         // [BB, SS, HH]  (holds xproj+bias on entry)
{
    extern __shared__ float sm[];
    float* whs  = sm;                 // [RPC][WST]
    float* as   = sm + WH_F;          // [BPC][AST]
    float* psum = sm + WH_F + A_F;    // [8][PP]

    const int c     = blockIdx.x;
    const int rgrp  = c & 31;         // 0..31
    const int bgrp  = c >> 5;         // 0..3
    const int crow0 = rgrp << 4;      // *16
    const int cb0   = bgrp << 3;      // *8
    unsigned* bar = &g_bars[bgrp * 256];   // 1KB apart: distinct L2 slices

    const int tid    = threadIdx.x;
    const int w      = tid >> 5;
    const int l      = tid & 31;
    const int rowg   = l & 7;
    const int batchg = l >> 3;

    // Load Wh slice: 16 rows x 512 -> smem with stride WST
    for (int i = tid; i < RPC * (HH / 4); i += RTHREADS) {
        int rr = i >> 7;               // /128 float4-per-row
        int kk = (i & 127) << 2;
        float4 v = *reinterpret_cast<const float4*>(
            Wh + (size_t)(crow0 + rr) * HH + kk);
        *reinterpret_cast<float4*>(whs + rr * WST + kk) = v;
    }

    // Owner setup (tid < 128): tid = batch*16 + row
    const int orow = tid & 15;
    const int obat = tid >> 4;
    float  tinv  = 0.0f;
    size_t obase = 0;
    size_t aidx  = 0;
    if (tid < 128) {
        int rg = crow0 + orow;
        int bg = cb0 + obat;
        tinv  = 1.0f / tau[rg];
        obase = (size_t)bg * SS * HH + rg;
        aidx  = (size_t)bg * HH + rg;
    }

    const float* wa = whs + rowg * WST + w * 64;        // row rowg
    const float* wb = whs + (rowg + 8) * WST + w * 64;  // row rowg+8
    const float* a0 = as + batchg * AST + w * 64;       // batch batchg
    const float* a1 = as + (batchg + 4) * AST + w * 64; // batch batchg+4
    const int pbase = batchg * 16 + rowg;

    __syncthreads();

    float h  = 0.0f;
    float xp = (tid < 128) ? __ldg(out + obase) : 0.0f;  // xproj for t = 0
    unsigned target = 0;

    for (int t = 0; t < SS; t++) {
        // ---- prefetch next xproj FIRST: joins the same MLP batch as the
        // stage LDGs below (5 outstanding loads, one exposed L2 round trip).
        float xp_next = 0.0f;
        if (tid < 128 && t + 1 < SS)
            xp_next = __ldg(out + obase + (size_t)(t + 1) * HH);

        // ---- stage a[cb0..cb0+7][:] (contiguous 16KB) into smem ------------
        // Batched: issue ALL 4 LDGs (MLP>=4 guaranteed at SASS level), then
        // the 4 STSs.
        {
            const float4* src = reinterpret_cast<const float4*>(
                &g_a[t & 1][cb0 * HH]);
            float4 v[4];
#pragma unroll
            for (int j = 0; j < 4; j++)
                v[j] = __ldcg(src + tid + j * RTHREADS);
#pragma unroll
            for (int j = 0; j < 4; j++) {
                int i = tid + j * RTHREADS;          // 0..1023 float4s
                int bl = i >> 7;
                int kk = (i & 127) << 2;
                *reinterpret_cast<float4*>(as + bl * AST + kk) = v[j];
            }
        }
        __syncthreads();

        // ---- 2x2 block, 64-k segment, 8 FFMA2 chains -----------------------
        long long s0 = 0, s1 = 0, s2 = 0, s3 = 0;
        long long s4 = 0, s5 = 0, s6 = 0, s7 = 0;
#pragma unroll 8
        for (int k = 0; k < 64; k += 4) {
            longlong2 va = *reinterpret_cast<const longlong2*>(wa + k);
            longlong2 vb = *reinterpret_cast<const longlong2*>(wb + k);
            longlong2 u0 = *reinterpret_cast<const longlong2*>(a0 + k);
            longlong2 u1 = *reinterpret_cast<const longlong2*>(a1 + k);
            FMA_F32X2(s0, va.x, u0.x, s0);
            FMA_F32X2(s1, va.y, u0.y, s1);
            FMA_F32X2(s2, va.x, u1.x, s2);
            FMA_F32X2(s3, va.y, u1.y, s3);
            FMA_F32X2(s4, vb.x, u0.x, s4);
            FMA_F32X2(s5, vb.y, u0.y, s5);
            FMA_F32X2(s6, vb.x, u1.x, s6);
            FMA_F32X2(s7, vb.y, u1.y, s7);
        }
        {
            float2 f0 = *reinterpret_cast<float2*>(&s0);
            float2 f1 = *reinterpret_cast<float2*>(&s1);
            float2 f2 = *reinterpret_cast<float2*>(&s2);
            float2 f3 = *reinterpret_cast<float2*>(&s3);
            float2 f4 = *reinterpret_cast<float2*>(&s4);
            float2 f5 = *reinterpret_cast<float2*>(&s5);
            float2 f6 = *reinterpret_cast<float2*>(&s6);
            float2 f7 = *reinterpret_cast<float2*>(&s7);
            float* pw = psum + w * PP;
            pw[pbase]      = (f0.x + f0.y) + (f1.x + f1.y); // (rowg,   batchg)
            pw[pbase + 8]  = (f4.x + f4.y) + (f5.x + f5.y); // (rowg+8, batchg)
            pw[pbase + 64] = (f2.x + f2.y) + (f3.x + f3.y); // (rowg,   batchg+4)
            pw[pbase + 72] = (f6.x + f6.y) + (f7.x + f7.y); // (rowg+8, batchg+4)
        }
        __syncthreads();

        // ---- owners finish the step (pairwise tree: 3 dependent levels) ---
        if (tid < 128) {
            float p0 = psum[0 * PP + tid], p1 = psum[1 * PP + tid];
            float p2 = psum[2 * PP + tid], p3 = psum[3 * PP + tid];
            float p4 = psum[4 * PP + tid], p5 = psum[5 * PP + tid];
            float p6 = psum[6 * PP + tid], p7 = psum[7 * PP + tid];
            float acc = ((p0 + p1) + (p2 + p3)) + ((p4 + p5) + (p6 + p7));
            // Euler step, dt = 1, bias already folded into xp
            h = h + (xp + acc - h) * tinv;
            // Publish tanh(h) for t+1 FIRST — the inter-CTA critical value.
            __stcg(&g_a[(t + 1) & 1][aidx], tanhf(h));
        }

        // ---- 32-CTA batch-group barrier (release/acquire chain) -----------
        // weak g_a stores -> bar.sync (CTA-scope acq_rel) -> tid0
        // red.release.gpu : cumulative release publishes the CTA's writes.
        __syncthreads();
        if (tid == 0) {
            target += GRPCTAS;
            asm volatile("red.release.gpu.global.add.u32 [%0], %1;"
                         :: "l"(bar), "r"(1u) : "memory");
        }
        // Work that only feeds OUR next iteration overlaps the wait.
        if (tid < 128) {
            out[obase + (size_t)t * HH] = h;
            xp = xp_next;
        }
        if (tid == 0) {
            unsigned v;
            while (true) {
                asm volatile("ld.acquire.gpu.global.u32 %0, [%1];"
                             : "=r"(v) : "l"(bar) : "memory");
                if ((int)(v - target) >= 0) break;
            }
        }
        __syncthreads();
    }
}

// ---------------- launch ----------------------------------------------------
extern "C" void kernel_launch(void* const* d_in, const int* in_sizes, int n_in,
                              void* d_out, int out_size) {
    const float* x    = (const float*)d_in[0];  // [32, 2048, 256]
    const float* Wx   = (const float*)d_in[1];  // [512, 256]
    const float* Wh   = (const float*)d_in[2];  // [512, 512]
    const float* tau  = (const float*)d_in[3];  // [512]
    const float* bias = (const float*)d_in[4];  // [512]
    float* out = (float*)d_out;                 // [32, 2048, 512]

    // Unconditional (no static guards): host-side attribute set, idempotent,
    // not a stream op -> capture-safe.
    cudaFuncSetAttribute(ltc_recur_kernel,
                         cudaFuncAttributeMaxDynamicSharedMemorySize,
                         RSMEM_BYTES);

    init_kernel<<<64, 256>>>();

    dim3 ggrid((BB * SS) / BM, HH / BN);        // (1024, 8)
    xproj_kernel<<<ggrid, 256>>>(x, Wx, bias, out);

    ltc_recur_kernel<<<NCTA, RTHREADS, RSMEM_BYTES>>>(Wh, tau, out);
}